// round 14
// baseline (speedup 1.0000x reference)
#include <cuda_runtime.h>
#include <cstdint>

// Problem constants (fixed by setup_inputs)
#define Nn     4
#define Cc     64
#define Hh     192
#define Ww     192
#define OUTC   3
#define Ss     4
#define SS2    16
#define CK     576         // C*9
#define WCOLS  48          // s*s*outC
#define HIDDEN 256
#define M2     1728
#define HOUT   768
#define WOUT   768

// Dynamic conv weights, g_w[k][sp*3+o], k = c*9 + i*3 + j
__device__ float g_w[CK * WCOLS];

// ---------------------------------------------------------------------------
// Stage 1: Pos2Weight MLP. grid = (16 subpixels, 8 m-chunks), block = 256.
// ---------------------------------------------------------------------------
__global__ void mlp_kernel(const float* __restrict__ W1, const float* __restrict__ b1,
                           const float* __restrict__ W2, const float* __restrict__ b2) {
    __shared__ float hidden[HIDDEN];
    const int sp = blockIdx.x;
    const int chunk = blockIdx.y;
    const int tid = threadIdx.x;

    const float p0 = 0.25f;
    const float p1 = (float)(sp >> 2) * 0.25f;
    const float p2 = (float)(sp & 3) * 0.25f;

    float h = fmaf(p0, W1[tid], fmaf(p1, W1[256 + tid], fmaf(p2, W1[512 + tid], b1[tid])));
    hidden[tid] = fmaxf(h, 0.0f);
    __syncthreads();

    if (tid < 216) {
        const int m = chunk * 216 + tid;
        float sum = b2[m];
        #pragma unroll 8
        for (int j = 0; j < HIDDEN; ++j)
            sum = fmaf(hidden[j], W2[j * M2 + m], sum);
        const int k = m / 3;
        const int o = m - k * 3;
        g_w[k * WCOLS + sp * 3 + o] = sum;
    }
}

// ---------------------------------------------------------------------------
// f32x2 packed-math helpers
// ---------------------------------------------------------------------------
typedef unsigned long long u64;

__device__ __forceinline__ u64 f2dup(float v) {
    u64 r;
    asm("mov.b64 %0, {%1, %1};" : "=l"(r) : "f"(v));
    return r;
}
__device__ __forceinline__ u64 ffma2(u64 a, u64 b, u64 c) {
    u64 d;
    asm("fma.rn.f32x2 %0, %1, %2, %3;" : "=l"(d) : "l"(a), "l"(b), "l"(c));
    return d;
}
__device__ __forceinline__ void f2unpack(u64 v, float& lo, float& hi) {
    asm("mov.b64 {%0, %1}, %2;" : "=f"(lo), "=f"(hi) : "l"(v));
}

// ---------------------------------------------------------------------------
// Stage 2: fused dynamic conv + pixel shuffle.
// Tile 32x16 px, grid (6, 12, 4); 512 threads (16 warps, 4 warps/SMSP).
//   warp = (wq = wid>>2 row band, og = wid&3 col group)  -> og warp-uniform
//   thread = 4x1 pixel strip (rows wq*4..+4, col = lane) x 12 cols
//   channels processed in 2 phases of 32 (smem can't hold all 64)
// smem: weights 27648 f + input chunk 32*18*36 = 20736 f  (193,536 B)
// ---------------------------------------------------------------------------
#define TW 32
#define TH 16
#define PH 32                           // channels per phase
#define SXROW 36
#define SXC (18 * SXROW)                // 648
#define SX_FLOATS (PH * SXC)            // 20736
#define SW_FLOATS (CK * WCOLS)          // 27648
#define STAGE_FLOATS (OUTC * 64 * 128)  // 24576
#define SMEM_BYTES ((SW_FLOATS + SX_FLOATS) * 4)

__global__ void __launch_bounds__(512, 1)
conv_kernel(const float* __restrict__ in, float* __restrict__ out) {
    extern __shared__ float smem[];
    float* sw = smem;                   // [576][48]
    float* sx = smem + SW_FLOATS;       // [32][18][36] (34 cols valid)

    const int tw = blockIdx.x, th = blockIdx.y, n = blockIdx.z;
    const int tid = threadIdx.x;

    // --- load weights (float4, coalesced) ---
    {
        const float4* gw4 = (const float4*)g_w;
        float4* sw4 = (float4*)sw;
        for (int i = tid; i < SW_FLOATS / 4; i += 512) sw4[i] = gw4[i];
    }

    const int wid  = tid >> 5;
    const int lane = tid & 31;
    const int og   = wid & 3;           // warp-uniform col group: cols [og*12, og*12+12)
    const int wq   = wid >> 2;          // 4-row band: rows [wq*4, wq*4+4)

    u64 acc[4][6];
    #pragma unroll
    for (int r = 0; r < 4; ++r)
        #pragma unroll
        for (int cp = 0; cp < 6; ++cp) acc[r][cp] = 0ull;

    const int gh0 = th * TH - 1, gw0 = tw * TW - 1;

    #pragma unroll 1
    for (int ph = 0; ph < 2; ++ph) {
        __syncthreads();   // sx free (prev phase fully consumed / first entry orders sw too)

        // --- load 18x34 halo chunk for channels [ph*32, ph*32+32), stride 36 ---
        {
            const float* inb = in + ((size_t)n * Cc + ph * PH) * Hh * Ww;
            for (int i = tid; i < PH * 18 * 34; i += 512) {
                int c = i / (18 * 34), r = i - c * (18 * 34);
                int lh = r / 34, lw = r - lh * 34;
                int gh = gh0 + lh, gw = gw0 + lw;
                float v = 0.0f;
                if ((unsigned)gh < (unsigned)Hh && (unsigned)gw < (unsigned)Ww)
                    v = inb[(c * Hh + gh) * Ww + gw];
                sx[c * SXC + lh * SXROW + lw] = v;
            }
        }
        __syncthreads();

        const float* xp0 = sx + wq * 4 * SXROW + lane;
        const float* wp0 = sw + (ph * PH) * 9 * WCOLS + og * 12;

        #pragma unroll 1
        for (int c = 0; c < PH; ++c) {
            // 6x3 input patch, broadcast-packed into f32x2
            const float* xp = xp0 + c * SXC;
            u64 P[6][3];
            #pragma unroll
            for (int rr = 0; rr < 6; ++rr)
                #pragma unroll
                for (int qq = 0; qq < 3; ++qq)
                    P[rr][qq] = f2dup(xp[rr * SXROW + qq]);

            const float* wc = wp0 + c * 9 * WCOLS;
            #pragma unroll
            for (int i = 0; i < 3; ++i) {
                #pragma unroll
                for (int j = 0; j < 3; ++j) {
                    const ulonglong2* wv = (const ulonglong2*)(wc + (i * 3 + j) * WCOLS);
                    ulonglong2 a = wv[0], b = wv[1], d = wv[2];
                    u64 Wp[6] = {a.x, a.y, b.x, b.y, d.x, d.y};
                    #pragma unroll
                    for (int r = 0; r < 4; ++r)
                        #pragma unroll
                        for (int cp = 0; cp < 6; ++cp)
                            acc[r][cp] = ffma2(P[i + r][j], Wp[cp], acc[r][cp]);
                }
            }
        }
    }

    __syncthreads();   // all smem free; reuse as output staging
    float* stage = smem;                // [3*64 rows][128 floats]

    // --- scatter accumulators into pixel-shuffled staging layout ---
    // rowid = o*64 + hl*4 + si (si == og); col = wl*4 + sj
    #pragma unroll
    for (int r = 0; r < 4; ++r) {
        const int hl = wq * 4 + r, wl = lane;
        #pragma unroll
        for (int cp = 0; cp < 6; ++cp) {
            float lo, hi;
            f2unpack(acc[r][cp], lo, hi);
            #pragma unroll
            for (int e = 0; e < 2; ++e) {
                const int col = og * 12 + 2 * cp + e;   // = sp*3 + o
                const int sp = col / 3;
                const int o  = col - sp * 3;
                const int sj = sp & 3;
                stage[(o * 64 + hl * 4 + og) * 128 + wl * 4 + sj] = (e == 0) ? lo : hi;
            }
        }
    }
    __syncthreads();

    // --- coalesced float4 stores: each stage row is 128 contiguous output floats ---
    {
        float* outb = out + (size_t)n * OUTC * HOUT * WOUT;
        const float4* st4 = (const float4*)stage;
        #pragma unroll
        for (int v = tid; v < STAGE_FLOATS / 4; v += 512) {
            const int flat = v * 4;
            const int rowid = flat >> 7;        // o*64 + hl*4 + si
            const int cc = flat & 127;
            const int o = rowid >> 6;
            const int rr2 = rowid & 63;
            const int hl = rr2 >> 2;
            const int si = rr2 & 3;
            const int gh = (th * TH + hl) * Ss + si;
            const int gw = tw * TW * Ss + cc;
            *(float4*)(outb + ((size_t)o * HOUT + gh) * WOUT + gw) = st4[v];
        }
    }
}

// ---------------------------------------------------------------------------
extern "C" void kernel_launch(void* const* d_in, const int* in_sizes, int n_in,
                              void* d_out, int out_size) {
    const float* x  = (const float*)d_in[0];
    const float* W1 = (const float*)d_in[1];
    const float* b1 = (const float*)d_in[2];
    const float* W2 = (const float*)d_in[3];
    const float* b2 = (const float*)d_in[4];
    float* out = (float*)d_out;

    mlp_kernel<<<dim3(SS2, 8), 256>>>(W1, b1, W2, b2);

    cudaFuncSetAttribute(conv_kernel, cudaFuncAttributeMaxDynamicSharedMemorySize, SMEM_BYTES);
    conv_kernel<<<dim3(Ww / TW, Hh / TH, Nn), 512, SMEM_BYTES>>>(x, out);
}

// round 16
// speedup vs baseline: 2.0129x; 2.0129x over previous
#include <cuda_runtime.h>
#include <cstdint>

// Problem constants
#define Nn 4
#define Cc 64
#define Hh 192
#define Ww 192
#define OUTC 3
#define HOUT 768
#define WOUT 768
#define KTOT 576
#define NCOLS 48
#define HIDDEN 256
#define M2 1728

// Conv tile: 16x16 pixels = 256 GEMM rows, 48 cols, K = 576 (k' = pos*64 + c)
#define TP 16
#define HALO 18
#define HALO_POS (HALO * HALO)     // 324
#define HSTRIDE 68                 // floats per halo position (64 ch + 4 pad)
#define BSTRIDE 580                // floats per weight column (576 + 4 pad)

// smem: B [48][580] then halo [324][68]; epilogue stage reuses base
#define SW_FLOATS (NCOLS * BSTRIDE)        // 27840
#define HALO_OFF  SW_FLOATS
#define SMEM_FLOATS (SW_FLOATS + HALO_POS * HSTRIDE)   // 49872
#define SMEM_BYTES (SMEM_FLOATS * 4)                   // 199488

// Dynamic weights as GEMM B: g_w[col][k'], col = sp*3+o, k' = pos*64+c, tf32-rounded
__device__ __align__(16) float g_w[NCOLS * KTOT];

// ---------------------------------------------------------------------------
// Stage 1: Pos2Weight MLP -> g_w[col][pos*64+c], tf32-rounded (rna).
// ---------------------------------------------------------------------------
__global__ void mlp_kernel(const float* __restrict__ W1, const float* __restrict__ b1,
                           const float* __restrict__ W2, const float* __restrict__ b2) {
    __shared__ float hidden[HIDDEN];
    const int sp = blockIdx.x;
    const int chunk = blockIdx.y;
    const int tid = threadIdx.x;

    const float p0 = 0.25f;
    const float p1 = (float)(sp >> 2) * 0.25f;
    const float p2 = (float)(sp & 3) * 0.25f;

    float h = fmaf(p0, W1[tid], fmaf(p1, W1[256 + tid], fmaf(p2, W1[512 + tid], b1[tid])));
    hidden[tid] = fmaxf(h, 0.0f);
    __syncthreads();

    if (tid < 216) {
        const int m = chunk * 216 + tid;
        float sum = b2[m];
        #pragma unroll 8
        for (int j = 0; j < HIDDEN; ++j)
            sum = fmaf(hidden[j], W2[j * M2 + m], sum);
        const int k = m / 3;
        const int o = m - k * 3;
        const int c = k / 9;
        const int pos = k - c * 9;
        uint32_t tv;
        asm("cvt.rna.tf32.f32 %0, %1;" : "=r"(tv) : "f"(sum));
        ((uint32_t*)g_w)[(sp * 3 + o) * KTOT + pos * 64 + c] = tv;
    }
}

// ---------------------------------------------------------------------------
// tf32 warp MMA: D[16x8] += A[16x8] * B[8x8]   (row.col)
// ---------------------------------------------------------------------------
__device__ __forceinline__ void mma_tf32(float* d, const uint32_t* a, const uint32_t* b) {
    asm volatile(
        "mma.sync.aligned.m16n8k8.row.col.f32.tf32.tf32.f32 "
        "{%0,%1,%2,%3}, {%4,%5,%6,%7}, {%8,%9}, {%0,%1,%2,%3};"
        : "+f"(d[0]), "+f"(d[1]), "+f"(d[2]), "+f"(d[3])
        : "r"(a[0]), "r"(a[1]), "r"(a[2]), "r"(a[3]), "r"(b[0]), "r"(b[1]));
}

// ---------------------------------------------------------------------------
// Stage 2: tf32 mma.sync GEMM + pixel shuffle.
// grid (12, 12, 4), 256 threads (8 warps).
// Warp wr: rows [wr*32, wr*32+32) (pixel rows pi = wr*2, wr*2+1), all 48 cols.
// Per k8-step: 8 A LDS + 12 B LDS (both conflict-free), 12 MMAs.
// ---------------------------------------------------------------------------
__global__ void __launch_bounds__(256, 1)
conv_kernel(const float* __restrict__ in, float* __restrict__ out) {
    extern __shared__ float smem[];
    float* sw = smem;                      // [48][580]
    float* hs = smem + HALO_OFF;           // [324][68]

    const int tw = blockIdx.x, th = blockIdx.y, n = blockIdx.z;
    const int tid = threadIdx.x;
    const int wr = tid >> 5, lane = tid & 31;
    const int g = lane >> 2, t = lane & 3;

    // --- B: copy g_w [48][576] -> smem [48][580] (float4) ---
    {
        const float4* gw4 = (const float4*)g_w;
        for (int i = tid; i < NCOLS * 144; i += 256) {
            const int col = i / 144, q = i - col * 144;
            *(float4*)(sw + col * BSTRIDE + q * 4) = gw4[i];
        }
    }
    // --- halo: [pos = lh*18+lw][c], stride 68, zero-padded, tf32-rounded ---
    {
        const int gh0 = th * TP - 1, gw0 = tw * TP - 1;
        const float* inb = in + (size_t)n * Cc * Hh * Ww;
        uint32_t* hu = (uint32_t*)hs;
        for (int i = tid; i < Cc * HALO_POS; i += 256) {
            const int c = i / HALO_POS, r = i - c * HALO_POS;
            const int lh = r / HALO, lw = r - lh * HALO;
            const int gh = gh0 + lh, gw = gw0 + lw;
            float v = 0.0f;
            if ((unsigned)gh < (unsigned)Hh && (unsigned)gw < (unsigned)Ww)
                v = inb[(c * Hh + gh) * Ww + gw];
            uint32_t tv;
            asm("cvt.rna.tf32.f32 %0, %1;" : "=r"(tv) : "f"(v));
            hu[r * HSTRIDE + c] = tv;
        }
    }
    __syncthreads();

    // Lane-fixed base pointers.
    // A element (row = wr*32 + mt*16 + g (+8), k' = pos*64 + c0 + t (+4)):
    //   addr = ((pi+di)*18 + (pj+dj))*68 + c,  pi = wr*2+mt, pj = g (+8)
    const uint32_t* hA = (const uint32_t*)hs + ((wr * 2) * HALO + g) * HSTRIDE + t;
    const uint32_t* bB = (const uint32_t*)sw + g * BSTRIDE + t;

    float acc[2][6][4];
    #pragma unroll
    for (int mt = 0; mt < 2; ++mt)
        #pragma unroll
        for (int nt = 0; nt < 6; ++nt)
            #pragma unroll
            for (int r = 0; r < 4; ++r) acc[mt][nt][r] = 0.0f;

    #pragma unroll 1
    for (int pos = 0; pos < 9; ++pos) {
        const int di = pos / 3, dj = pos - di * 3;
        const uint32_t* ha = hA + (di * HALO + dj) * HSTRIDE;
        const uint32_t* bb = bB + pos * 64;

        #pragma unroll 1
        for (int cb = 0; cb < 8; ++cb) {
            const int c0 = cb * 8;
            uint32_t a[2][4];
            #pragma unroll
            for (int mt = 0; mt < 2; ++mt) {
                const uint32_t* hm = ha + mt * (TP * HALO * HSTRIDE / TP) * 0 + mt * (18 * HSTRIDE) + c0;
                a[mt][0] = hm[0];
                a[mt][1] = hm[8 * HSTRIDE];
                a[mt][2] = hm[4];
                a[mt][3] = hm[8 * HSTRIDE + 4];
            }
            uint32_t b[6][2];
            #pragma unroll
            for (int nt = 0; nt < 6; ++nt) {
                b[nt][0] = bb[nt * 8 * BSTRIDE + c0];
                b[nt][1] = bb[nt * 8 * BSTRIDE + c0 + 4];
            }
            #pragma unroll
            for (int mt = 0; mt < 2; ++mt)
                #pragma unroll
                for (int nt = 0; nt < 6; ++nt)
                    mma_tf32(acc[mt][nt], a[mt], b[nt]);
        }
    }

    __syncthreads();           // smem free; reuse as staging
    float* stage = smem;       // [192 rows][64 floats] = 48 KB

    // --- scatter accumulators into pixel-shuffled staging layout ---
    // row = o*64 + hl*4 + si ; col = wl*4 + sj   (hl,wl = tile-local pixel)
    #pragma unroll
    for (int mt = 0; mt < 2; ++mt) {
        const int hl = wr * 2 + mt;
        #pragma unroll
        for (int nt = 0; nt < 6; ++nt) {
            #pragma unroll
            for (int r = 0; r < 4; ++r) {
                const int wl = g + ((r >> 1) << 3);          // g or g+8
                const int col = nt * 8 + 2 * t + (r & 1);    // = sp*3 + o
                const int sp = col / 3;
                const int o  = col - sp * 3;
                const int si = sp >> 2, sj = sp & 3;
                stage[(o * 64 + hl * 4 + si) * 64 + wl * 4 + sj] = acc[mt][nt][r];
            }
        }
    }
    __syncthreads();

    // --- coalesced float4 stores: each stage row = 64 contiguous output floats ---
    {
        float* outb = out + (size_t)n * OUTC * HOUT * WOUT;
        const float4* st4 = (const float4*)stage;
        #pragma unroll
        for (int v = tid; v < 192 * 16; v += 256) {
            const int flat = v * 4;
            const int row = flat >> 6, cc = flat & 63;
            const int o = row >> 6, rr = row & 63;
            const int hl = rr >> 2, si = rr & 3;
            const int gh = (th * TP + hl) * 4 + si;
            const int gw = tw * 64 + cc;
            *(float4*)(outb + ((size_t)o * HOUT + gh) * WOUT + gw) = st4[v];
        }
    }
}

// ---------------------------------------------------------------------------
extern "C" void kernel_launch(void* const* d_in, const int* in_sizes, int n_in,
                              void* d_out, int out_size) {
    const float* x  = (const float*)d_in[0];
    const float* W1 = (const float*)d_in[1];
    const float* b1 = (const float*)d_in[2];
    const float* W2 = (const float*)d_in[3];
    const float* b2 = (const float*)d_in[4];
    float* out = (float*)d_out;

    mlp_kernel<<<dim3(16, 8), 256>>>(W1, b1, W2, b2);

    cudaFuncSetAttribute(conv_kernel, cudaFuncAttributeMaxDynamicSharedMemorySize, SMEM_BYTES);
    conv_kernel<<<dim3(Ww / TP, Hh / TP, Nn), 256, SMEM_BYTES>>>(x, out);
}